// round 5
// baseline (speedup 1.0000x reference)
#include <cuda_runtime.h>
#include <cuda_bf16.h>

// SKA: spatially-varying 3x3 grouped conv.
// x: (B=8, C=64, H=128, W=128) f32
// w: (B=8, C_w=8, 9, H, W) f32
// out[b, g*8+cw, h, col] = sum_{i,j} x_pad[b, g*8+cw, h+i-1, col+j-1] * w[b, cw, i*3+j, h, col]
//
// Block = 128 threads = 4 warps, all serving one (b, cw, h). Warp q handles
// groups {q, q+4}. All 4 warps read the SAME 9 weight rows -> L1 reuse.
// Each thread issues 15 independent LDG.128 up front (9 w + 6 x), then two
// short FMA chunks. Lane = 4-wide column chunk; horizontal halo via shuffle.

#define B_   8
#define C_   64
#define H_   128
#define W_   128
#define CW_  8
#define G_   8
#define HW_  (H_ * W_)

__global__ void __launch_bounds__(128) ska_kernel(
    const float* __restrict__ x,
    const float* __restrict__ w,
    float* __restrict__ out)
{
    int tid  = threadIdx.x;
    int lane = tid & 31;
    int q    = tid >> 5;              // warp id in block: groups q and q+4
    int blk  = blockIdx.x;
    int h    = blk & 127;
    int cw   = (blk >> 7) & 7;
    int b    = blk >> 10;
    int col0 = lane << 2;

    const bool top = (h > 0);
    const bool bot = (h < H_ - 1);
    const float4 z4 = make_float4(0.f, 0.f, 0.f, 0.f);

    const int c0 = q * CW_ + cw;
    const int c1 = (q + 4) * CW_ + cw;
    const float* xr0 = x + ((size_t)(b * C_ + c0)) * HW_ + h * W_ + col0;
    const float* xr1 = x + ((size_t)(b * C_ + c1)) * HW_ + h * W_ + col0;

    // ---- issue all 15 independent loads up front ----
    float4 v[2][3];
    v[0][1] = *reinterpret_cast<const float4*>(xr0);
    v[1][1] = *reinterpret_cast<const float4*>(xr1);
    v[0][0] = top ? *reinterpret_cast<const float4*>(xr0 - W_) : z4;
    v[1][0] = top ? *reinterpret_cast<const float4*>(xr1 - W_) : z4;
    v[0][2] = bot ? *reinterpret_cast<const float4*>(xr0 + W_) : z4;
    v[1][2] = bot ? *reinterpret_cast<const float4*>(xr1 + W_) : z4;

    const float* wbase = w + ((size_t)(b * CW_ + cw) * 9) * HW_ + h * W_ + col0;
    float4 wv[9];
#pragma unroll
    for (int k = 0; k < 9; k++) {
        wv[k] = *reinterpret_cast<const float4*>(wbase + (size_t)k * HW_);
    }

    float* ob = out + (size_t)b * C_ * HW_ + h * W_ + col0;

#pragma unroll
    for (int p = 0; p < 2; p++) {
        float acc0 = 0.f, acc1 = 0.f, acc2 = 0.f, acc3 = 0.f;
#pragma unroll
        for (int di = 0; di < 3; di++) {
            float L = __shfl_up_sync(0xffffffffu, v[p][di].w, 1);
            float R = __shfl_down_sync(0xffffffffu, v[p][di].x, 1);
            if (lane == 0)  L = 0.f;
            if (lane == 31) R = 0.f;

            float4 wl = wv[di * 3 + 0];
            float4 wc = wv[di * 3 + 1];
            float4 wr = wv[di * 3 + 2];

            acc0 = fmaf(L,          wl.x, acc0);
            acc0 = fmaf(v[p][di].x, wc.x, acc0);
            acc0 = fmaf(v[p][di].y, wr.x, acc0);

            acc1 = fmaf(v[p][di].x, wl.y, acc1);
            acc1 = fmaf(v[p][di].y, wc.y, acc1);
            acc1 = fmaf(v[p][di].z, wr.y, acc1);

            acc2 = fmaf(v[p][di].y, wl.z, acc2);
            acc2 = fmaf(v[p][di].z, wc.z, acc2);
            acc2 = fmaf(v[p][di].w, wr.z, acc2);

            acc3 = fmaf(v[p][di].z, wl.w, acc3);
            acc3 = fmaf(v[p][di].w, wc.w, acc3);
            acc3 = fmaf(R,          wr.w, acc3);
        }

        int c = (q + p * 4) * CW_ + cw;
        float4 o;
        o.x = acc0; o.y = acc1; o.z = acc2; o.w = acc3;
        *reinterpret_cast<float4*>(ob + (size_t)c * HW_) = o;
    }
}

extern "C" void kernel_launch(void* const* d_in, const int* in_sizes, int n_in,
                              void* d_out, int out_size) {
    const float* x = (const float*)d_in[0];
    const float* w = (const float*)d_in[1];
    float* out = (float*)d_out;

    int blocks = B_ * CW_ * H_;   // 8192 blocks
    ska_kernel<<<blocks, 128>>>(x, w, out);
}